// round 2
// baseline (speedup 1.0000x reference)
#include <cuda_runtime.h>
#include <cuda_bf16.h>

// ============================================================================
// TFCRNN teacher-forcing GRU. B=32, T=512, IN=256, H=2048, C=16.
// Persistent single-kernel design: 128 CTAs x 256 threads, all co-resident,
// software grid barrier. 2 graph nodes total (reset + persistent).
//
// Math identities used:
//   scheduled prob == 0.9f exactly for every t  -> flag = rand < 900
//   sigmoid(v) > 0.5  <=>  v > 0
// Layouts:
//   h state : pair-packed float2 g_h[buf][k2*32 + b] = (h[2k2][b], h[2k2+1][b])
//   tf      : g_tf[c*32 + b]
// ============================================================================

typedef unsigned long long ull;

#define BATCH 32
#define TSTEPS 512
#define INF 256
#define HID 2048
#define CLS 16
#define NCTA 128
#define NTHR 256
#define CHUNK 256  // k-chunk staged in smem (256 k x 32 b x 4B = 32KB)

__device__ float2 g_h[2][(HID / 2) * BATCH];
__device__ float g_tf[CLS * BATCH];
__device__ unsigned g_bar_count;
__device__ unsigned g_bar_gen;

// ---------------- packed f32x2 helpers --------------------------------------
__device__ __forceinline__ ull ffma2(ull a, ull b, ull c) {
    ull d;
    asm("fma.rn.f32x2 %0, %1, %2, %3;" : "=l"(d) : "l"(a), "l"(b), "l"(c));
    return d;
}
__device__ __forceinline__ float2 unpack2(ull v) {
    float2 f;
    asm("mov.b64 {%0, %1}, %2;" : "=f"(f.x), "=f"(f.y) : "l"(v));
    return f;
}
__device__ __forceinline__ float sigmoidf_(float v) {
    return 1.0f / (1.0f + expf(-v));
}

// ---------------- grid barrier ----------------------------------------------
// All NCTA CTAs are co-resident (grid <= #SMs, 1 CTA/SM). Generation-based.
// __threadfence() (gpu scope) both publishes stores and emits CCTL.IVALL so
// post-barrier reads don't hit stale L1 lines of the ping-pong buffers.
__device__ __forceinline__ void grid_barrier(unsigned& gen) {
    __syncthreads();
    if (threadIdx.x == 0) {
        __threadfence();
        unsigned arr = atomicAdd(&g_bar_count, 1u);
        if (arr == NCTA - 1) {
            g_bar_count = 0;
            __threadfence();
            atomicExch(&g_bar_gen, gen + 1);
        } else {
            unsigned g;
            do {
                asm volatile("ld.acquire.gpu.u32 %0, [%1];"
                             : "=r"(g) : "l"(&g_bar_gen) : "memory");
            } while (g == gen);
        }
        __threadfence();  // invalidate L1 so whole CTA sees fresh data
    }
    gen++;
    __syncthreads();
}

// ---------------- reset (per launch) ----------------------------------------
__global__ void reset_kernel() {
    g_bar_count = 0;
    g_bar_gen = 0;
}

// ---------------- persistent kernel -----------------------------------------
__global__ __launch_bounds__(NTHR, 1) void tfcrnn_persistent(
    const float* __restrict__ x, const float* __restrict__ y,
    const int* __restrict__ rand_vals, const float* __restrict__ W_ih,
    const float* __restrict__ W_hh, const float* __restrict__ b_ih,
    const float* __restrict__ b_hh, const float* __restrict__ W_cls,
    const float* __restrict__ b_cls, float* __restrict__ out) {
    const int tid = threadIdx.x;
    const int lane = tid & 31;
    const int wid = tid >> 5;
    const int cta = blockIdx.x;
    unsigned gen = 0;

    __shared__ float2 s_h[(CHUNK / 2) * BATCH];  // 4096 float2 = 32KB
    __shared__ float s_part[8][BATCH];

    // ---- init state (h0 = 0, tf0 = 0) ----
    for (int i = cta * NTHR + tid; i < (HID / 2) * BATCH; i += NCTA * NTHR)
        g_h[0][i] = make_float2(0.0f, 0.0f);
    for (int i = cta * NTHR + tid; i < CLS * BATCH; i += NCTA * NTHR)
        g_tf[i] = 0.0f;
    grid_barrier(gen);

    // This warp owns hidden units u0, u0+1.
    const int u0 = cta * 16 + wid * 2;

    // W_hh row pointers (stride HID), rows r/z/n for both units.
    const float* Hr0 = W_hh + (size_t)u0 * HID;
    const float* Hr1 = W_hh + (size_t)(u0 + 1) * HID;
    const float* Hz0 = W_hh + (size_t)(HID + u0) * HID;
    const float* Hz1 = W_hh + (size_t)(HID + u0 + 1) * HID;
    const float* Hn0 = W_hh + (size_t)(2 * HID + u0) * HID;
    const float* Hn1 = W_hh + (size_t)(2 * HID + u0 + 1) * HID;
    // W_ih row pointers (stride 272).
    const float* Ir0 = W_ih + (size_t)u0 * 272;
    const float* Ir1 = W_ih + (size_t)(u0 + 1) * 272;
    const float* Iz0 = W_ih + (size_t)(HID + u0) * 272;
    const float* Iz1 = W_ih + (size_t)(HID + u0 + 1) * 272;
    const float* In0 = W_ih + (size_t)(2 * HID + u0) * 272;
    const float* In1 = W_ih + (size_t)(2 * HID + u0 + 1) * 272;

    const float bR0 = b_ih[u0] + b_hh[u0];
    const float bR1 = b_ih[u0 + 1] + b_hh[u0 + 1];
    const float bZ0 = b_ih[HID + u0] + b_hh[HID + u0];
    const float bZ1 = b_ih[HID + u0 + 1] + b_hh[HID + u0 + 1];
    const float bI0 = b_ih[2 * HID + u0];
    const float bI1 = b_ih[2 * HID + u0 + 1];
    const float bN0 = b_hh[2 * HID + u0];
    const float bN1 = b_hh[2 * HID + u0 + 1];

    const float* xb = x + (size_t)lane * TSTEPS * INF;  // + t*INF per step

    for (int t = 0; t < TSTEPS; t++) {
        const float2* __restrict__ hp = g_h[t & 1];
        float2* __restrict__ hout = g_h[(t + 1) & 1];

        ull aR0 = 0, aR1 = 0, aZ0 = 0, aZ1 = 0;
        ull aI0 = 0, aI1 = 0, aN0 = 0, aN1 = 0;

        // ---- x segment: k = 0..255 (contributes to R, Z, I) ----
        const float* xt = xb + (size_t)t * INF;
#pragma unroll 4
        for (int k = 0; k < INF; k += 4) {
            ull x0 = *(const ull*)(xt + k);
            ull x1 = *(const ull*)(xt + k + 2);
            ulonglong2 w;
            w = *(const ulonglong2*)(Ir0 + k);
            aR0 = ffma2(x0, w.x, aR0); aR0 = ffma2(x1, w.y, aR0);
            w = *(const ulonglong2*)(Ir1 + k);
            aR1 = ffma2(x0, w.x, aR1); aR1 = ffma2(x1, w.y, aR1);
            w = *(const ulonglong2*)(Iz0 + k);
            aZ0 = ffma2(x0, w.x, aZ0); aZ0 = ffma2(x1, w.y, aZ0);
            w = *(const ulonglong2*)(Iz1 + k);
            aZ1 = ffma2(x0, w.x, aZ1); aZ1 = ffma2(x1, w.y, aZ1);
            w = *(const ulonglong2*)(In0 + k);
            aI0 = ffma2(x0, w.x, aI0); aI0 = ffma2(x1, w.y, aI0);
            w = *(const ulonglong2*)(In1 + k);
            aI1 = ffma2(x0, w.x, aI1); aI1 = ffma2(x1, w.y, aI1);
        }

        // ---- h segment: k = 0..2047, staged through smem in CHUNK chunks ----
        for (int kc = 0; kc < HID; kc += CHUNK) {
            __syncthreads();
            {  // cooperative copy: 4096 float2 contiguous (float4 moves)
                const float4* src = (const float4*)(hp + (kc / 2) * BATCH);
                float4* dst = (float4*)s_h;
#pragma unroll
                for (int i = 0; i < (CHUNK / 2) * BATCH / 2 / NTHR; i++)
                    dst[tid + i * NTHR] = src[tid + i * NTHR];
            }
            __syncthreads();
            const ull* hs = (const ull*)s_h;
#pragma unroll 2
            for (int k = 0; k < CHUNK; k += 4) {
                ull h0 = hs[k * 16 + lane];
                ull h1 = hs[k * 16 + 32 + lane];
                ulonglong2 w;
                w = *(const ulonglong2*)(Hr0 + kc + k);
                aR0 = ffma2(h0, w.x, aR0); aR0 = ffma2(h1, w.y, aR0);
                w = *(const ulonglong2*)(Hr1 + kc + k);
                aR1 = ffma2(h0, w.x, aR1); aR1 = ffma2(h1, w.y, aR1);
                w = *(const ulonglong2*)(Hz0 + kc + k);
                aZ0 = ffma2(h0, w.x, aZ0); aZ0 = ffma2(h1, w.y, aZ0);
                w = *(const ulonglong2*)(Hz1 + kc + k);
                aZ1 = ffma2(h0, w.x, aZ1); aZ1 = ffma2(h1, w.y, aZ1);
                w = *(const ulonglong2*)(Hn0 + kc + k);
                aN0 = ffma2(h0, w.x, aN0); aN0 = ffma2(h1, w.y, aN0);
                w = *(const ulonglong2*)(Hn1 + kc + k);
                aN1 = ffma2(h0, w.x, aN1); aN1 = ffma2(h1, w.y, aN1);
            }
        }

        // ---- horizontal sums + biases ----
        float2 f;
        f = unpack2(aR0); float sR0 = f.x + f.y + bR0;
        f = unpack2(aR1); float sR1 = f.x + f.y + bR1;
        f = unpack2(aZ0); float sZ0 = f.x + f.y + bZ0;
        f = unpack2(aZ1); float sZ1 = f.x + f.y + bZ1;
        f = unpack2(aI0); float sI0 = f.x + f.y + bI0;
        f = unpack2(aI1); float sI1 = f.x + f.y + bI1;
        f = unpack2(aN0); float sN0 = f.x + f.y + bN0;
        f = unpack2(aN1); float sN1 = f.x + f.y + bN1;

        // ---- tf segment: cols 256..271 of W_ih (contributes to R, Z, I) ----
#pragma unroll
        for (int j = 0; j < CLS; j++) {
            float tv = g_tf[j * 32 + lane];
            sR0 = fmaf(tv, Ir0[INF + j], sR0);
            sR1 = fmaf(tv, Ir1[INF + j], sR1);
            sZ0 = fmaf(tv, Iz0[INF + j], sZ0);
            sZ1 = fmaf(tv, Iz1[INF + j], sZ1);
            sI0 = fmaf(tv, In0[INF + j], sI0);
            sI1 = fmaf(tv, In1[INF + j], sI1);
        }

        // ---- gates + state update ----
        float2 hprev = unpack2(((const ull*)hp)[(u0 >> 1) * 32 + lane]);
        float r0 = sigmoidf_(sR0), r1 = sigmoidf_(sR1);
        float z0 = sigmoidf_(sZ0), z1 = sigmoidf_(sZ1);
        float n0 = tanhf(sI0 + r0 * sN0);
        float n1 = tanhf(sI1 + r1 * sN1);
        float hn0 = (1.0f - z0) * n0 + z0 * hprev.x;
        float hn1 = (1.0f - z1) * n1 + z1 * hprev.y;
        hout[(u0 >> 1) * 32 + lane] = make_float2(hn0, hn1);

        grid_barrier(gen);  // h(t) visible everywhere

        // ---- classifier + teacher forcing: CTA c < 16 owns class c ----
        if (cta < CLS) {
            const int c = cta;
            const float2* __restrict__ hc = g_h[(t + 1) & 1];
            const float* __restrict__ Wc = W_cls + (size_t)c * HID;
            float part = 0.0f;
            const int k2b = wid * 128;
#pragma unroll 8
            for (int k2 = k2b; k2 < k2b + 128; k2++) {
                float2 hv = hc[k2 * 32 + lane];  // coalesced
                part = fmaf(hv.x, Wc[2 * k2], part);
                part = fmaf(hv.y, Wc[2 * k2 + 1], part);
            }
            s_part[wid][lane] = part;
            __syncthreads();
            if (wid == 0) {
                float tot = b_cls[c];
#pragma unroll
                for (int w = 0; w < 8; w++) tot += s_part[w][lane];
                const int b = lane;
                out[((size_t)b * TSTEPS + t) * CLS + c] = tot;
                float pred = (tot > 0.0f) ? 1.0f : 0.0f;  // sigmoid>0.5 <=> >0
                bool flag = rand_vals[t * BATCH + b] < 900;  // prob == 0.9
                g_tf[c * 32 + b] =
                    flag ? y[((size_t)b * TSTEPS + t) * CLS + c] : pred;
            }
        }

        grid_barrier(gen);  // tf(t) visible everywhere
    }
}

// ---------------- launch ----------------------------------------------------
extern "C" void kernel_launch(void* const* d_in, const int* in_sizes, int n_in,
                              void* d_out, int out_size) {
    const float* x     = (const float*)d_in[0];
    const float* y     = (const float*)d_in[1];
    const int*   rv    = (const int*)d_in[2];
    const float* W_ih  = (const float*)d_in[3];
    const float* W_hh  = (const float*)d_in[4];
    const float* b_ih  = (const float*)d_in[5];
    const float* b_hh  = (const float*)d_in[6];
    const float* W_cls = (const float*)d_in[7];
    const float* b_cls = (const float*)d_in[8];
    float* out = (float*)d_out;

    reset_kernel<<<1, 1>>>();
    tfcrnn_persistent<<<NCTA, NTHR>>>(x, y, rv, W_ih, W_hh, b_ih, b_hh, W_cls,
                                      b_cls, out);
}

// round 3
// speedup vs baseline: 2.3903x; 2.3903x over previous
#include <cuda_runtime.h>
#include <cuda_bf16.h>

// ============================================================================
// TFCRNN teacher-forcing GRU. B=32, T=512, IN=256, H=2048, C=16.
// Persistent kernel, 128 CTAs x 256 thr (all co-resident), 1 grid barrier/step.
//
// GEMV restructured lane-over-k: every W / h load is a coalesced 512B
// LDG.128 across the warp (vs lane-uniform 16B loads in R2 which made the
// kernel LSU-issue bound at fma=11.7%).
//
// Identities: scheduled prob == 0.9 for all t -> flag = rand < 900;
//             sigmoid(v) > 0.5 <=> v > 0.
// Layouts: h[buf][b*2048 + k] (b-major, coalesced for lane-over-k reads)
//          tf[c*32 + b]
// ============================================================================

typedef unsigned long long ull;

#define BATCH 32
#define TSTEPS 512
#define INF 256
#define HID 2048
#define CLS 16
#define NCTA 128
#define NTHR 256

__device__ float g_h[2][BATCH * HID];
__device__ float g_tf[CLS * BATCH];
__device__ unsigned g_bar_count, g_bar_gen, g_tf_flag;

// ---------------- packed f32x2 helpers --------------------------------------
__device__ __forceinline__ ull ffma2(ull a, ull b, ull c) {
    ull d;
    asm("fma.rn.f32x2 %0, %1, %2, %3;" : "=l"(d) : "l"(a), "l"(b), "l"(c));
    return d;
}
__device__ __forceinline__ float2 unpack2(ull v) {
    float2 f;
    asm("mov.b64 {%0, %1}, %2;" : "=f"(f.x), "=f"(f.y) : "l"(v));
    return f;
}
__device__ __forceinline__ float sigmoidf_(float v) {
    return 1.0f / (1.0f + expf(-v));
}

// ---------------- warp reduce-scatter: 8 values over 32 lanes ---------------
// Input: v[0..7] per-lane partials for 8 batch slots. Output: this lane's
// total for slot bb = 4*bit4(lane,16) + 2*bit(lane,8) + 1*bit(lane,4)
// (each slot duplicated in 4 lanes; lanes with (lane&3)==0 store).
__device__ __forceinline__ float reduce_scatter8(float* v, int lane) {
#pragma unroll
    for (int j = 0; j < 4; j++) {
        float t0 = __shfl_xor_sync(0xffffffffu, v[j], 16);
        float t1 = __shfl_xor_sync(0xffffffffu, v[j + 4], 16);
        v[j] = (lane & 16) ? v[j + 4] + t1 : v[j] + t0;
    }
#pragma unroll
    for (int j = 0; j < 2; j++) {
        float t0 = __shfl_xor_sync(0xffffffffu, v[j], 8);
        float t1 = __shfl_xor_sync(0xffffffffu, v[j + 2], 8);
        v[j] = (lane & 8) ? v[j + 2] + t1 : v[j] + t0;
    }
    float t0 = __shfl_xor_sync(0xffffffffu, v[0], 4);
    float t1 = __shfl_xor_sync(0xffffffffu, v[1], 4);
    float r = (lane & 4) ? v[1] + t1 : v[0] + t0;
    r += __shfl_xor_sync(0xffffffffu, r, 2);
    r += __shfl_xor_sync(0xffffffffu, r, 1);
    return r;
}

// ---------------- grid barrier ----------------------------------------------
__device__ __forceinline__ void grid_barrier(unsigned& gen) {
    __syncthreads();
    if (threadIdx.x == 0) {
        __threadfence();
        unsigned arr = atomicAdd(&g_bar_count, 1u);
        if (arr == NCTA - 1) {
            g_bar_count = 0;
            __threadfence();
            atomicExch(&g_bar_gen, gen + 1);
        } else {
            unsigned g;
            do {
                asm volatile("ld.acquire.gpu.u32 %0, [%1];"
                             : "=r"(g) : "l"(&g_bar_gen) : "memory");
            } while (g == gen);
        }
        __threadfence();  // CCTL.IVALL: no stale L1 for cross-SM data
    }
    gen++;
    __syncthreads();
}

// ---------------- reset (per launch) ----------------------------------------
__global__ void reset_kernel() {
    int i = blockIdx.x * blockDim.x + threadIdx.x;
    if (i < BATCH * HID) g_h[0][i] = 0.0f;
    if (i < CLS * BATCH) g_tf[i] = 0.0f;
    if (i == 0) { g_bar_count = 0; g_bar_gen = 0; g_tf_flag = 0; }
}

// ---------------- persistent kernel -----------------------------------------
__global__ __launch_bounds__(NTHR, 1) void tfcrnn_persistent(
    const float* __restrict__ x, const float* __restrict__ y,
    const int* __restrict__ rand_vals, const float* __restrict__ W_ih,
    const float* __restrict__ W_hh, const float* __restrict__ b_ih,
    const float* __restrict__ b_hh, const float* __restrict__ W_cls,
    const float* __restrict__ b_cls, float* __restrict__ out) {
    const int tid = threadIdx.x;
    const int lane = tid & 31;
    const int wid = tid >> 5;
    const int cta = blockIdx.x;
    unsigned gen = 0;

    __shared__ float s_red[8][6][32];   // [warp][row][b]: R0 R1 Z0 Z1 N0 N1
    __shared__ float s_redI[8][2][32];  // [warp][unit][b]: i_n part

    const int u0 = cta * 16 + wid * 2;  // warp owns units u0, u0+1

    const float bR0 = b_ih[u0] + b_hh[u0];
    const float bR1 = b_ih[u0 + 1] + b_hh[u0 + 1];
    const float bZ0 = b_ih[HID + u0] + b_hh[HID + u0];
    const float bZ1 = b_ih[HID + u0 + 1] + b_hh[HID + u0 + 1];
    const float bI0 = b_ih[2 * HID + u0];
    const float bI1 = b_ih[2 * HID + u0 + 1];
    const float bN0 = b_hh[2 * HID + u0];
    const float bN1 = b_hh[2 * HID + u0 + 1];

    const int bbsel =
        (((lane >> 4) & 1) << 2) | (((lane >> 3) & 1) << 1) | ((lane >> 2) & 1);
    const bool storer = (lane & 3) == 0;

    for (int t = 0; t < TSTEPS; t++) {
        const float* __restrict__ hin = g_h[t & 1];
        float* __restrict__ hout = g_h[(t + 1) & 1];

        for (int c8 = 0; c8 < 4; c8++) {  // batch chunk of 8
            const int bB = c8 * 8;
            ull acc[6][8];
#pragma unroll
            for (int r = 0; r < 6; r++)
#pragma unroll
                for (int bb = 0; bb < 8; bb++) acc[r][bb] = 0ull;

            // ---- x passes: k = 0..255 (rows R,Z,I of W_ih) ----
#pragma unroll
            for (int p = 0; p < 2; p++) {
                const int ko = p * 128 + lane * 4;
                ulonglong2 sv[8];
#pragma unroll
                for (int bb = 0; bb < 8; bb++)
                    sv[bb] = *(const ulonglong2*)(
                        x + ((size_t)(bB + bb) * TSTEPS + t) * INF + ko);
#pragma unroll
                for (int r = 0; r < 6; r++) {
                    ulonglong2 w = *(const ulonglong2*)(
                        W_ih + (size_t)((r >> 1) * HID + u0 + (r & 1)) * 272 +
                        ko);
#pragma unroll
                    for (int bb = 0; bb < 8; bb++) {
                        acc[r][bb] = ffma2(sv[bb].x, w.x, acc[r][bb]);
                        acc[r][bb] = ffma2(sv[bb].y, w.y, acc[r][bb]);
                    }
                }
            }
            // reduce i_n rows (4,5) now; reuse their acc slots for h_n
#pragma unroll
            for (int r = 4; r < 6; r++) {
                float v[8];
#pragma unroll
                for (int bb = 0; bb < 8; bb++) {
                    float2 f = unpack2(acc[r][bb]);
                    v[bb] = f.x + f.y;
                    acc[r][bb] = 0ull;
                }
                float tot = reduce_scatter8(v, lane);
                if (storer) s_redI[wid][r - 4][bB + bbsel] = tot;
            }

            // ---- h passes: k = 0..2047 (rows R,Z,N of W_hh) ----
#pragma unroll 2
            for (int p = 0; p < 16; p++) {
                const int ko = p * 128 + lane * 4;
                ulonglong2 sv[8];
#pragma unroll
                for (int bb = 0; bb < 8; bb++)
                    sv[bb] = *(const ulonglong2*)(hin +
                                                  (size_t)(bB + bb) * HID + ko);
#pragma unroll
                for (int r = 0; r < 6; r++) {
                    ulonglong2 w = *(const ulonglong2*)(
                        W_hh + (size_t)((r >> 1) * HID + u0 + (r & 1)) * HID +
                        ko);
#pragma unroll
                    for (int bb = 0; bb < 8; bb++) {
                        acc[r][bb] = ffma2(sv[bb].x, w.x, acc[r][bb]);
                        acc[r][bb] = ffma2(sv[bb].y, w.y, acc[r][bb]);
                    }
                }
            }
            // reduce R,Z,N rows
#pragma unroll
            for (int r = 0; r < 6; r++) {
                float v[8];
#pragma unroll
                for (int bb = 0; bb < 8; bb++) {
                    float2 f = unpack2(acc[r][bb]);
                    v[bb] = f.x + f.y;
                }
                float tot = reduce_scatter8(v, lane);
                if (storer) s_red[wid][r][bB + bbsel] = tot;
            }
        }
        __syncwarp();

        // ---- wait for tf(t-1) (hidden under the GEMV above) ----
        if (tid == 0) {
            unsigned thr = 16u * (unsigned)t, v;
            do {
                asm volatile("ld.acquire.gpu.u32 %0, [%1];"
                             : "=r"(v) : "l"(&g_tf_flag) : "memory");
            } while (v < thr);
            __threadfence();
        }
        __syncthreads();

        // ---- tf segment (16 cols of W_ih), b = lane ----
        float tfa[6] = {0, 0, 0, 0, 0, 0};
#pragma unroll
        for (int j = 0; j < 16; j += 4) {
            float tv0 = g_tf[(j + 0) * 32 + lane];
            float tv1 = g_tf[(j + 1) * 32 + lane];
            float tv2 = g_tf[(j + 2) * 32 + lane];
            float tv3 = g_tf[(j + 3) * 32 + lane];
#pragma unroll
            for (int r = 0; r < 6; r++) {
                float4 w = *(const float4*)(
                    W_ih + (size_t)((r >> 1) * HID + u0 + (r & 1)) * 272 + INF +
                    j);
                tfa[r] = fmaf(
                    tv0, w.x,
                    fmaf(tv1, w.y, fmaf(tv2, w.z, fmaf(tv3, w.w, tfa[r]))));
            }
        }

        // ---- gates + state update, b = lane ----
        {
            const int b = lane;
            float sR0 = s_red[wid][0][b] + tfa[0] + bR0;
            float sR1 = s_red[wid][1][b] + tfa[1] + bR1;
            float sZ0 = s_red[wid][2][b] + tfa[2] + bZ0;
            float sZ1 = s_red[wid][3][b] + tfa[3] + bZ1;
            float sN0 = s_red[wid][4][b] + bN0;
            float sN1 = s_red[wid][5][b] + bN1;
            float sI0 = s_redI[wid][0][b] + tfa[4] + bI0;
            float sI1 = s_redI[wid][1][b] + tfa[5] + bI1;
            float hp0 = hin[(size_t)b * HID + u0];
            float hp1 = hin[(size_t)b * HID + u0 + 1];
            float r0 = sigmoidf_(sR0), r1 = sigmoidf_(sR1);
            float z0 = sigmoidf_(sZ0), z1 = sigmoidf_(sZ1);
            float n0 = tanhf(sI0 + r0 * sN0);
            float n1 = tanhf(sI1 + r1 * sN1);
            float hn0 = (1.0f - z0) * n0 + z0 * hp0;
            float hn1 = (1.0f - z1) * n1 + z1 * hp1;
            *(float2*)(hout + (size_t)b * HID + u0) = make_float2(hn0, hn1);
        }

        grid_barrier(gen);  // h(t) complete & visible

        // ---- classifier + teacher forcing: CTA c < 16 owns class c ----
        if (cta < CLS) {
            const int c = cta;
            const int b0 = wid * 4;
            ull a4[4] = {0, 0, 0, 0};
#pragma unroll 4
            for (int it = 0; it < 16; it++) {
                const int ko = it * 128 + lane * 4;
                ulonglong2 w =
                    *(const ulonglong2*)(W_cls + (size_t)c * HID + ko);
#pragma unroll
                for (int bb = 0; bb < 4; bb++) {
                    ulonglong2 hv = *(const ulonglong2*)(
                        hout + (size_t)(b0 + bb) * HID + ko);
                    a4[bb] = ffma2(hv.x, w.x, a4[bb]);
                    a4[bb] = ffma2(hv.y, w.y, a4[bb]);
                }
            }
#pragma unroll
            for (int bb = 0; bb < 4; bb++) {
                float2 f = unpack2(a4[bb]);
                float s = f.x + f.y;
                s += __shfl_xor_sync(0xffffffffu, s, 16);
                s += __shfl_xor_sync(0xffffffffu, s, 8);
                s += __shfl_xor_sync(0xffffffffu, s, 4);
                s += __shfl_xor_sync(0xffffffffu, s, 2);
                s += __shfl_xor_sync(0xffffffffu, s, 1);
                if (lane == 0) {
                    const int b = b0 + bb;
                    float tot = s + b_cls[c];
                    out[((size_t)b * TSTEPS + t) * CLS + c] = tot;
                    float pred = (tot > 0.0f) ? 1.0f : 0.0f;
                    bool fl = rand_vals[t * BATCH + b] < 900;
                    g_tf[c * 32 + b] =
                        fl ? y[((size_t)b * TSTEPS + t) * CLS + c] : pred;
                }
            }
            __syncthreads();
            if (tid == 0) {
                __threadfence();
                atomicAdd(&g_tf_flag, 1u);
            }
        }
    }
}

// ---------------- launch ----------------------------------------------------
extern "C" void kernel_launch(void* const* d_in, const int* in_sizes, int n_in,
                              void* d_out, int out_size) {
    const float* x     = (const float*)d_in[0];
    const float* y     = (const float*)d_in[1];
    const int*   rv    = (const int*)d_in[2];
    const float* W_ih  = (const float*)d_in[3];
    const float* W_hh  = (const float*)d_in[4];
    const float* b_ih  = (const float*)d_in[5];
    const float* b_hh  = (const float*)d_in[6];
    const float* W_cls = (const float*)d_in[7];
    const float* b_cls = (const float*)d_in[8];
    float* out = (float*)d_out;

    reset_kernel<<<128, 512>>>();
    tfcrnn_persistent<<<NCTA, NTHR>>>(x, y, rv, W_ih, W_hh, b_ih, b_hh, W_cls,
                                      b_cls, out);
}